// round 13
// baseline (speedup 1.0000x reference)
#include <cuda_runtime.h>

#define HH 8192
#define WW 512
#define NPIX (HH * WW)
#define HB 4096
#define WB 256
#define NBLK (HB * WB)
#define NTILE 1024   // (8192/32) tile rows * (512/128) tile cols
#define TG22F 0.4142135623730951f

#define TSW 128
#define TSH 32
#define IMW_S 136   // simg cols: global w0-4 .. w0+131 (Sobel uses j=2..133)
#define IMH 36
#define MGW 130     // mag cols: w0-1 .. w0+128
#define MGW_S 132
#define MGH 34
#define NSTAGE (3 * IMH * 34)   // 3672 float4 slots
#define NLBLK 1024              // local blocks per tile (16 rows x 64 cols)

// Static scratch
__device__ unsigned char g_bmask[NBLK];  // b0-3: weak(w00,w01,w10,w11); b4: strong
__device__ int           g_blabel[NBLK];
__device__ unsigned char g_bflag[NBLK];
__device__ int           g_scnt[NTILE];          // strong-local-root count per tile
__device__ int           g_slist[NTILE * NLBLK]; // compacted strong-local-root global ids

__device__ __forceinline__ int bytev(unsigned v, int k) { return (int)((v >> (8 * k)) & 0xFF); }

// exact XLA op order: floor(((v+1)*0.5)*255) then clip [0,255].
// __float2int_rd == floor for all finite t here; clamp in int (alu pipe).
__device__ __forceinline__ unsigned cvt_u8(float v) {
    float t = __fmul_rn(__fmul_rn(__fadd_rn(v, 1.0f), 0.5f), 255.0f);
    int i = __float2int_rd(t);
    return (unsigned)min(max(i, 0), 255);
}

// ---- shared-memory union-find (tile-local CCL) ----
__device__ __forceinline__ int lfind(int* L, int x) {
    int p = L[x];
    while (p != x) {
        int gp = L[p];
        if (gp != p) L[x] = gp;
        x = p; p = gp;
    }
    return x;
}
__device__ __forceinline__ int lfind_ro(const int* L, int x) {
    int p = L[x];
    while (p != x) { x = p; p = L[x]; }
    return x;
}
__device__ __forceinline__ void lunion(int* L, int a, int b) {
    a = lfind(L, a); b = lfind(L, b);
    while (a != b) {
        int hi = a > b ? a : b;
        int lo = a > b ? b : a;
        int old = atomicCAS(&L[hi], hi, lo);
        if (old == hi) break;
        a = lfind(L, old);
        b = lfind(L, lo);
    }
}

// K1: fused convert + int Sobel + argmax + NMS + block pack + TILE-LOCAL CCL + compaction
__global__ __launch_bounds__(256) void k_gradnms(const float* __restrict__ x) {
    __shared__ unsigned char  simg[3][IMH][IMW_S];   // 14.7 KB
    __shared__ unsigned short smd[MGH][MGW_S];       // 9.0 KB, (mag<<2)|dir
    __shared__ unsigned char  sbm[NLBLK];            // block masks (16x64)
    __shared__ int            slab[NLBLK];           // local UF labels
    __shared__ unsigned char  sstr[NLBLK];           // strong flag at local roots
    __shared__ int            scnt;

    int tile = blockIdx.x;
    int tw = tile & 3;                 // 512/128 = 4 tiles across
    int tr = tile >> 2;
    int r0 = tr * TSH, w0 = tw * TSW;
    int tid = threadIdx.x;
    if (tid == 0) scnt = 0;

    // ---- Stage image tile + halo as uint8 (34 float4 per row cover cols w0-4 .. w0+131) ----
#pragma unroll
    for (int k = 0; k < 15; k++) {
        int idx = tid + k * 256;
        if (idx < NSTAGE) {
            int c   = idx / (IMH * 34);
            int rem = idx - c * (IMH * 34);
            int iy  = rem / 34, qx = rem - iy * 34;
            int gr = min(max(r0 - 2 + iy, 0), HH - 1);
            int b = gr >> 9, h = gr & 511;
            const float* rowp = &x[(((size_t)(b * 3 + c) * 512 + h) * 512)];
            int gw0 = w0 - 4 + qx * 4;
            float4 v;
            if (gw0 >= 0 && gw0 <= 508) {
                v = __ldg((const float4*)&rowp[gw0]);
            } else {  // replicate-border clamp (edge slots only)
                v.x = __ldg(&rowp[min(max(gw0,     0), WW - 1)]);
                v.y = __ldg(&rowp[min(max(gw0 + 1, 0), WW - 1)]);
                v.z = __ldg(&rowp[min(max(gw0 + 2, 0), WW - 1)]);
                v.w = __ldg(&rowp[min(max(gw0 + 3, 0), WW - 1)]);
            }
            unsigned pk = cvt_u8(v.x) | (cvt_u8(v.y) << 8) | (cvt_u8(v.z) << 16) | (cvt_u8(v.w) << 24);
            *(unsigned*)&simg[c][iy][qx * 4] = pk;
        }
    }
    __syncthreads();

    // ---- Int Sobel + channel argmax, 4 mag pixels/quad (34 rows x 33 quads = 1122) ----
#pragma unroll
    for (int k = 0; k < 5; k++) {
        int q = tid + k * 256;
        if (q < MGH * 33) {
            int my = q / 33, qx = q - my * 33;
            int mx0 = qx * 4;
            int bm[4]  = {-1, -1, -1, -1};
            int bgx[4] = {0, 0, 0, 0}, bgy[4] = {0, 0, 0, 0};
#pragma unroll
            for (int c = 0; c < 3; c++) {
                const unsigned char* bp = &simg[c][my][mx0];
                unsigned t0 = *(const unsigned*)(bp);
                unsigned t1 = *(const unsigned*)(bp + 4);
                unsigned m0 = *(const unsigned*)(bp + IMW_S);
                unsigned m1 = *(const unsigned*)(bp + IMW_S + 4);
                unsigned b0 = *(const unsigned*)(bp + 2 * IMW_S);
                unsigned b1 = *(const unsigned*)(bp + 2 * IMW_S + 4);
                int cg[6], dr[6];
#pragma unroll
                for (int j = 0; j < 2; j++) {          // bytes 2,3 of word0
                    int tv = bytev(t0, j + 2), mv = bytev(m0, j + 2), bv = bytev(b0, j + 2);
                    cg[j] = tv + 2 * mv + bv;
                    dr[j] = bv - tv;
                }
#pragma unroll
                for (int j = 0; j < 4; j++) {          // bytes 0..3 of word1
                    int tv = bytev(t1, j), mv = bytev(m1, j), bv = bytev(b1, j);
                    cg[2 + j] = tv + 2 * mv + bv;
                    dr[2 + j] = bv - tv;
                }
#pragma unroll
                for (int p = 0; p < 4; p++) {
                    int gx = cg[p + 2] - cg[p];
                    int gy = dr[p] + 2 * dr[p + 1] + dr[p + 2];
                    int mm = abs(gx) + abs(gy);
                    if (mm > bm[p]) { bm[p] = mm; bgx[p] = gx; bgy[p] = gy; }  // first-max argmax
                }
            }
            unsigned short ov[4];
#pragma unroll
            for (int p = 0; p < 4; p++) {
                int mx = mx0 + p;
                int gr = r0 - 1 + my, gw = w0 - 1 + mx;
                unsigned short out = 0;
                if (mx < MGW && (unsigned)gr < (unsigned)HH && (unsigned)gw < (unsigned)WW) {
                    unsigned d;
                    float fgx = __int2float_rn(bgx[p]), fgy = __int2float_rn(bgy[p]);
                    float ax = fabsf(fgx), ay = fabsf(fgy);
                    if (ay < __fmul_rn(TG22F, ax))      d = 0;
                    else if (__fmul_rn(ay, TG22F) > ax) d = 1;
                    else d = (__fmul_rn(fgx, fgy) >= 0.0f) ? 2 : 3;
                    out = (unsigned short)(((unsigned)bm[p] << 2) | d);
                }
                ov[p] = out;
            }
            // packed quad store (two 32-bit stores; mx0*2 is 8B aligned, stride 264B)
            unsigned lo = (unsigned)ov[0] | ((unsigned)ov[1] << 16);
            unsigned hi = (unsigned)ov[2] | ((unsigned)ov[3] << 16);
            *(unsigned*)&smd[my][mx0]     = lo;
            *(unsigned*)&smd[my][mx0 + 2] = hi;
        }
    }
    __syncthreads();

    // ---- Fused NMS + thresholds + 2x2 block pack + UF init (4 blocks/thread) ----
#pragma unroll
    for (int k = 0; k < 4; k++) {
        int q = tid + k * 256;
        int byt = q >> 6, bxt = q & 63;
        unsigned char pm[2][2];
#pragma unroll
        for (int dy = 0; dy < 2; dy++) {
#pragma unroll
            for (int dx = 0; dx < 2; dx++) {
                int my = 2 * byt + dy + 1, mx = 2 * bxt + dx + 1;
                unsigned cmd = smd[my][mx];
                int m = cmd >> 2, d = cmd & 3;
                int n1, n2;
                if (d == 0)      { n1 = smd[my][mx - 1] >> 2;     n2 = smd[my][mx + 1] >> 2; }
                else if (d == 1) { n1 = smd[my - 1][mx] >> 2;     n2 = smd[my + 1][mx] >> 2; }
                else if (d == 2) { n1 = smd[my - 1][mx - 1] >> 2; n2 = smd[my + 1][mx + 1] >> 2; }
                else             { n1 = smd[my - 1][mx + 1] >> 2; n2 = smd[my + 1][mx - 1] >> 2; }
                bool keep = (m > n1) && (m >= n2);
                unsigned char msk = 0;
                if (keep && (m > 100)) msk = 1;
                if (keep && (m > 200)) msk = 3;
                pm[dy][dx] = msk;
            }
        }
        unsigned char bmv = (pm[0][0] & 1) | ((pm[0][1] & 1) << 1)
                          | ((pm[1][0] & 1) << 2) | ((pm[1][1] & 1) << 3);
        if ((pm[0][0] | pm[0][1] | pm[1][0] | pm[1][1]) & 2) bmv |= 0x10;
        sbm[q]  = bmv;
        slab[q] = q;
        sstr[q] = 0;
    }
    __syncthreads();

    // ---- Tile-local CCL over the 1024 blocks (E, S, SE, SW within tile) ----
#pragma unroll
    for (int k = 0; k < 4; k++) {
        int q = tid + k * 256;
        unsigned char m = sbm[q];
        if (!(m & 0xF)) continue;
        int byt = q >> 6, bxt = q & 63;
        if (bxt < 63 && (m & 0xA) && (sbm[q + 1]  & 0x5)) lunion(slab, q, q + 1);
        if (byt < 15) {
            if ((m & 0xC) && (sbm[q + 64] & 0x3)) lunion(slab, q, q + 64);
            if (bxt < 63 && (m & 0x8) && (sbm[q + 65] & 0x1)) lunion(slab, q, q + 65);
            if (bxt > 0  && (m & 0x4) && (sbm[q + 63] & 0x2)) lunion(slab, q, q + 63);
        }
    }
    __syncthreads();

    // ---- Propagate strong to local roots ----
#pragma unroll
    for (int k = 0; k < 4; k++) {
        int q = tid + k * 256;
        if (sbm[q] & 0x10) sstr[lfind_ro(slab, q)] = 1;
    }
    __syncthreads();

    // ---- Emit: global mask, labels -> local-root global id, compact strong roots ----
#pragma unroll
    for (int k = 0; k < 4; k++) {
        int q = tid + k * 256;
        int byt = q >> 6, bxt = q & 63;
        int bi = (tr * 16 + byt) * WB + (tw * 64 + bxt);
        unsigned char bmv = sbm[q];
        if (bmv & 0xF) {
            int lr = lfind_ro(slab, q);
            if (lr == q && sstr[q]) {
                int idx = atomicAdd(&scnt, 1);
                g_slist[tile * NLBLK + idx] = bi;   // order nondeterministic; flag writes idempotent
            }
            int byr = lr >> 6, bxr = lr & 63;
            g_blabel[bi] = (tr * 16 + byr) * WB + (tw * 64 + bxr);
            g_bflag[bi]  = 0;
        }
        g_bmask[bi] = bmv;
    }
    __syncthreads();
    if (tid == 0) g_scnt[tile] = scnt;
}

// ---- global union-find (cross-tile) ----
__device__ __forceinline__ int uf_find(int x) {
    int p = g_blabel[x];
    while (p != x) {
        int gp = g_blabel[p];
        if (gp != p) g_blabel[x] = gp;
        x = p; p = gp;
    }
    return x;
}
__device__ __forceinline__ int uf_find_ro(int x) {
    int p = g_blabel[x];
    while (p != x) { x = p; p = g_blabel[x]; }
    return x;
}
__device__ __forceinline__ void uf_union(int i, int j) {
    int a = uf_find(i), b = uf_find(j);
    while (a != b) {
        int hi = a > b ? a : b;
        int lo = a > b ? b : a;
        int old = atomicCAS(&g_blabel[hi], hi, lo);
        if (old == hi) break;
        a = uf_find(old);
        b = uf_find(lo);
    }
}

// K2: cross-tile merge over ENUMERATED border blocks only (94 per 16x64 tile)
#define NBORDER 94
__global__ __launch_bounds__(256) void k_merge() {
    int t = blockIdx.x * blockDim.x + threadIdx.x;
    if (t >= NTILE * NBORDER) return;
    int tile = t / NBORDER, slot = t - tile * NBORDER;
    int tr = tile >> 2, tw = tile & 3;
    int byt, bxt;
    if (slot < 64)      { byt = 15;        bxt = slot; }       // south row
    else if (slot < 79) { byt = slot - 64; bxt = 63;   }       // east col (byt 0..14)
    else                { byt = slot - 79; bxt = 0;    }       // west col (byt 0..14)
    int bx = tw * 64 + bxt, by = tr * 16 + byt;
    int bi = by * WB + bx;

    unsigned char m = g_bmask[bi];
    if (!(m & 0xF)) return;
    bool eB = (bxt == 63), sB = (byt == 15), wB = (bxt == 0);

    if (eB && bx + 1 < WB && (m & 0xA) && (g_bmask[bi + 1] & 0x5)) uf_union(bi, bi + 1);
    if (by + 1 < HB) {
        if (sB && (m & 0xC) && (g_bmask[bi + WB] & 0x3)) uf_union(bi, bi + WB);
        if ((sB | eB) && (m & 0x8) && bx + 1 < WB && (g_bmask[bi + WB + 1] & 0x1)) uf_union(bi, bi + WB + 1);
        if ((sB | wB) && (m & 0x4) && bx > 0 && (g_bmask[bi + WB - 1] & 0x2)) uf_union(bi, bi + WB - 1);
    }
}

// K3: compacted — only strong local roots walk to their final root
__global__ __launch_bounds__(64) void k_sflag() {
    int tile = blockIdx.x;
    int cnt = g_scnt[tile];
    for (int i = threadIdx.x; i < cnt; i += 64)
        g_bflag[uf_find_ro(g_slist[tile * NLBLK + i])] = 1;
}

// K4: ±1 output, 8 pixels/thread (2x4 patch = both rows of 2 blocks), 6x float4 stores
__global__ __launch_bounds__(256) void k_out(float* __restrict__ out) {
    int t = blockIdx.x * blockDim.x + threadIdx.x;   // NPIX/8 threads
    if (t >= NPIX / 8) return;
    int pw = t & 127, py = t >> 7;
    int bi0 = py * WB + pw * 2;

    unsigned char m0 = g_bmask[bi0], m1 = g_bmask[bi0 + 1];
    bool f0 = false, f1 = false;
    if (m0 & 0xF) f0 = (g_bflag[uf_find_ro(bi0)] != 0);
    if (m1 & 0xF) f1 = (g_bflag[uf_find_ro(bi0 + 1)] != 0);

    float4 v0 = make_float4(((m0 & 1) && f0) ? 1.0f : -1.0f,
                            ((m0 & 2) && f0) ? 1.0f : -1.0f,
                            ((m1 & 1) && f1) ? 1.0f : -1.0f,
                            ((m1 & 2) && f1) ? 1.0f : -1.0f);
    float4 v1 = make_float4(((m0 & 4) && f0) ? 1.0f : -1.0f,
                            ((m0 & 8) && f0) ? 1.0f : -1.0f,
                            ((m1 & 4) && f1) ? 1.0f : -1.0f,
                            ((m1 & 8) && f1) ? 1.0f : -1.0f);

    int r = py * 2;                       // top pixel row (r and r+1 in same image)
    int b = r >> 9, h = r & 511;
    size_t base = ((size_t)(b * 3) * 512 + h) * 512 + pw * 4;
    *(float4*)&out[base]                       = v0;
    *(float4*)&out[base + 512]                 = v1;
    *(float4*)&out[base + 512 * 512]           = v0;
    *(float4*)&out[base + 512 * 512 + 512]     = v1;
    *(float4*)&out[base + 2 * 512 * 512]       = v0;
    *(float4*)&out[base + 2 * 512 * 512 + 512] = v1;
}

extern "C" void kernel_launch(void* const* d_in, const int* in_sizes, int n_in,
                              void* d_out, int out_size) {
    const float* x = (const float*)d_in[0];
    float* out = (float*)d_out;
    k_gradnms<<<NTILE, 256>>>(x);
    k_merge<<<(NTILE * NBORDER + 255) / 256, 256>>>();
    k_sflag<<<NTILE, 64>>>();
    k_out<<<NPIX / 8 / 256, 256>>>(out);
}

// round 14
// speedup vs baseline: 1.2505x; 1.2505x over previous
#include <cuda_runtime.h>

#define HH 8192
#define WW 512
#define NPIX (HH * WW)
#define HB 4096
#define WB 256
#define NBLK (HB * WB)
#define NTILE 2048   // (8192/32) tile rows * (512/64) tile cols
#define TG22F 0.4142135623730951f

#define TSW 64
#define TSH 32
#define IMW_S 72  // simg cols: global w0-4 .. w0+67 (Sobel uses j=2..69)
#define IMH 36
#define MGW 66    // mag cols: w0-1 .. w0+64
#define MGW_S 68
#define MGH 34
#define NSTAGE (3 * IMH * 18)   // 1944 float4 slots

// Static scratch
__device__ unsigned char g_bmask[NBLK];  // b0-3: weak(w00,w01,w10,w11); b4: strong
__device__ int           g_blabel[NBLK];
__device__ unsigned char g_bflag[NBLK];
__device__ int           g_scnt[NTILE];        // strong-local-root count per tile
__device__ int           g_slist[NTILE * 512]; // compacted strong-local-root global ids

__device__ __forceinline__ int bytev(unsigned v, int k) { return (int)((v >> (8 * k)) & 0xFF); }

// exact XLA op order: floor(((v+1)*0.5)*255) then clip [0,255].
// __float2int_rd == floor for all finite t here; clamp in int (alu pipe).
__device__ __forceinline__ unsigned cvt_u8(float v) {
    float t = __fmul_rn(__fmul_rn(__fadd_rn(v, 1.0f), 0.5f), 255.0f);
    int i = __float2int_rd(t);
    return (unsigned)min(max(i, 0), 255);
}

// ---- shared-memory union-find (tile-local CCL) ----
__device__ __forceinline__ int lfind(int* L, int x) {
    int p = L[x];
    while (p != x) {
        int gp = L[p];
        if (gp != p) L[x] = gp;
        x = p; p = gp;
    }
    return x;
}
__device__ __forceinline__ int lfind_ro(const int* L, int x) {
    int p = L[x];
    while (p != x) { x = p; p = L[x]; }
    return x;
}
__device__ __forceinline__ void lunion(int* L, int a, int b) {
    a = lfind(L, a); b = lfind(L, b);
    while (a != b) {
        int hi = a > b ? a : b;
        int lo = a > b ? b : a;
        int old = atomicCAS(&L[hi], hi, lo);
        if (old == hi) break;
        a = lfind(L, old);
        b = lfind(L, lo);
    }
}

// K1: fused convert + int Sobel + argmax + NMS + block pack + TILE-LOCAL CCL + compaction
__global__ __launch_bounds__(256) void k_gradnms(const float* __restrict__ x) {
    __shared__ unsigned char  simg[3][IMH][IMW_S];
    __shared__ unsigned short smd[MGH][MGW_S];   // (mag<<2) | dir, packed
    __shared__ unsigned char  sbm[512];          // per-tile block masks (16x32 blocks)
    __shared__ int            slab[512];         // local UF labels
    __shared__ unsigned char  sstr[512];         // strong flag at local roots
    __shared__ int            scnt;              // strong-local-root counter

    int tile = blockIdx.x;
    int tw = tile & 7;                 // 512/64 = 8 tiles across
    int tr = tile >> 3;
    int r0 = tr * TSH, w0 = tw * TSW;
    int tid = threadIdx.x;
    if (tid == 0) scnt = 0;

    // ---- Stage image tile + halo as uint8, unrolled 8x for MLP ----
#pragma unroll
    for (int k = 0; k < 8; k++) {
        int idx = tid + k * 256;
        if (idx < NSTAGE) {
            int c   = idx / (IMH * 18);
            int rem = idx - c * (IMH * 18);
            int iy  = rem / 18, qx = rem - iy * 18;
            int gr = min(max(r0 - 2 + iy, 0), HH - 1);
            int b = gr >> 9, h = gr & 511;
            const float* rowp = &x[(((size_t)(b * 3 + c) * 512 + h) * 512)];
            int gw0 = w0 - 4 + qx * 4;
            float4 v;
            if (gw0 >= 0 && gw0 <= 508) {
                v = __ldg((const float4*)&rowp[gw0]);
            } else {  // replicate-border clamp, 4 scalar loads (edge-tile slots only)
                v.x = __ldg(&rowp[min(max(gw0,     0), WW - 1)]);
                v.y = __ldg(&rowp[min(max(gw0 + 1, 0), WW - 1)]);
                v.z = __ldg(&rowp[min(max(gw0 + 2, 0), WW - 1)]);
                v.w = __ldg(&rowp[min(max(gw0 + 3, 0), WW - 1)]);
            }
            unsigned pk = cvt_u8(v.x) | (cvt_u8(v.y) << 8) | (cvt_u8(v.z) << 16) | (cvt_u8(v.w) << 24);
            *(unsigned*)&simg[c][iy][qx * 4] = pk;
        }
    }
    __syncthreads();

    // ---- Int Sobel + channel argmax, 4 mag pixels/iter, unrolled 3x ----
    // mag col mx -> simg cols mx+2..mx+4 (simg col j = global w0-4+j)
#pragma unroll
    for (int k = 0; k < 3; k++) {
        int q = tid + k * 256;
        if (q >= MGH * 17) break;
        int my = q / 17, qx = q - my * 17;
        int mx0 = qx * 4;
        int bm[4]  = {-1, -1, -1, -1};
        int bgx[4] = {0, 0, 0, 0}, bgy[4] = {0, 0, 0, 0};
#pragma unroll
        for (int c = 0; c < 3; c++) {
            const unsigned char* bp = &simg[c][my][mx0];
            unsigned t0 = *(const unsigned*)(bp);
            unsigned t1 = *(const unsigned*)(bp + 4);
            unsigned m0 = *(const unsigned*)(bp + IMW_S);
            unsigned m1 = *(const unsigned*)(bp + IMW_S + 4);
            unsigned b0 = *(const unsigned*)(bp + 2 * IMW_S);
            unsigned b1 = *(const unsigned*)(bp + 2 * IMW_S + 4);
            int cg[6], dr[6];
#pragma unroll
            for (int j = 0; j < 2; j++) {          // bytes 2,3 of word0
                int tv = bytev(t0, j + 2), mv = bytev(m0, j + 2), bv = bytev(b0, j + 2);
                cg[j] = tv + 2 * mv + bv;
                dr[j] = bv - tv;
            }
#pragma unroll
            for (int j = 0; j < 4; j++) {          // bytes 0..3 of word1
                int tv = bytev(t1, j), mv = bytev(m1, j), bv = bytev(b1, j);
                cg[2 + j] = tv + 2 * mv + bv;
                dr[2 + j] = bv - tv;
            }
#pragma unroll
            for (int p = 0; p < 4; p++) {
                int gx = cg[p + 2] - cg[p];
                int gy = dr[p] + 2 * dr[p + 1] + dr[p + 2];
                int mm = abs(gx) + abs(gy);
                if (mm > bm[p]) { bm[p] = mm; bgx[p] = gx; bgy[p] = gy; }  // first-max argmax
            }
        }
        unsigned short ov[4];
#pragma unroll
        for (int p = 0; p < 4; p++) {
            int mx = mx0 + p;
            int gr = r0 - 1 + my, gw = w0 - 1 + mx;
            unsigned short out = 0;
            if (mx < MGW && (unsigned)gr < (unsigned)HH && (unsigned)gw < (unsigned)WW) {
                unsigned d;
                float fgx = __int2float_rn(bgx[p]), fgy = __int2float_rn(bgy[p]);
                float ax = fabsf(fgx), ay = fabsf(fgy);
                if (ay < __fmul_rn(TG22F, ax))      d = 0;
                else if (__fmul_rn(ay, TG22F) > ax) d = 1;
                else d = (__fmul_rn(fgx, fgy) >= 0.0f) ? 2 : 3;
                out = (unsigned short)(((unsigned)bm[p] << 2) | d);
            }
            ov[p] = out;
        }
        // packed quad store (two 32-bit stores; mx0*2 is 8B aligned, stride 136B)
        unsigned lo = (unsigned)ov[0] | ((unsigned)ov[1] << 16);
        unsigned hi = (unsigned)ov[2] | ((unsigned)ov[3] << 16);
        *(unsigned*)&smd[my][mx0]     = lo;
        *(unsigned*)&smd[my][mx0 + 2] = hi;
    }
    __syncthreads();

    // ---- Fused NMS + thresholds + 2x2 block pack + UF init (2 blocks/thread) ----
#pragma unroll
    for (int k = 0; k < 2; k++) {
        int q = tid + k * 256;
        int byt = q >> 5, bxt = q & 31;
        unsigned char pm[2][2];
#pragma unroll
        for (int dy = 0; dy < 2; dy++) {
#pragma unroll
            for (int dx = 0; dx < 2; dx++) {
                int my = 2 * byt + dy + 1, mx = 2 * bxt + dx + 1;
                unsigned cmd = smd[my][mx];
                int m = cmd >> 2, d = cmd & 3;
                int n1, n2;
                if (d == 0)      { n1 = smd[my][mx - 1] >> 2;     n2 = smd[my][mx + 1] >> 2; }
                else if (d == 1) { n1 = smd[my - 1][mx] >> 2;     n2 = smd[my + 1][mx] >> 2; }
                else if (d == 2) { n1 = smd[my - 1][mx - 1] >> 2; n2 = smd[my + 1][mx + 1] >> 2; }
                else             { n1 = smd[my - 1][mx + 1] >> 2; n2 = smd[my + 1][mx - 1] >> 2; }
                bool keep = (m > n1) && (m >= n2);
                unsigned char msk = 0;
                if (keep && (m > 100)) msk = 1;
                if (keep && (m > 200)) msk = 3;
                pm[dy][dx] = msk;
            }
        }
        unsigned char bmv = (pm[0][0] & 1) | ((pm[0][1] & 1) << 1)
                          | ((pm[1][0] & 1) << 2) | ((pm[1][1] & 1) << 3);
        if ((pm[0][0] | pm[0][1] | pm[1][0] | pm[1][1]) & 2) bmv |= 0x10;
        sbm[q]  = bmv;
        slab[q] = q;
        sstr[q] = 0;
    }
    __syncthreads();

    // ---- Tile-local CCL over the 512 blocks (E, S, SE, SW within tile) ----
#pragma unroll
    for (int k = 0; k < 2; k++) {
        int q = tid + k * 256;
        unsigned char m = sbm[q];
        if (!(m & 0xF)) continue;
        int byt = q >> 5, bxt = q & 31;
        if (bxt < 31 && (m & 0xA) && (sbm[q + 1]  & 0x5)) lunion(slab, q, q + 1);
        if (byt < 15) {
            if ((m & 0xC) && (sbm[q + 32] & 0x3)) lunion(slab, q, q + 32);
            if (bxt < 31 && (m & 0x8) && (sbm[q + 33] & 0x1)) lunion(slab, q, q + 33);
            if (bxt > 0  && (m & 0x4) && (sbm[q + 31] & 0x2)) lunion(slab, q, q + 31);
        }
    }
    __syncthreads();

    // ---- Propagate strong to local roots ----
#pragma unroll
    for (int k = 0; k < 2; k++) {
        int q = tid + k * 256;
        if (sbm[q] & 0x10) sstr[lfind_ro(slab, q)] = 1;
    }
    __syncthreads();

    // ---- Emit: global mask, labels -> local-root global id, compact strong roots ----
#pragma unroll
    for (int k = 0; k < 2; k++) {
        int q = tid + k * 256;
        int byt = q >> 5, bxt = q & 31;
        int bi = (tr * 16 + byt) * WB + (tw * 32 + bxt);
        unsigned char bmv = sbm[q];
        if (bmv & 0xF) {
            int lr = lfind_ro(slab, q);
            if (lr == q && sstr[q]) {
                int idx = atomicAdd(&scnt, 1);
                g_slist[tile * 512 + idx] = bi;    // list order nondeterministic; flag writes idempotent
            }
            int byr = lr >> 5, bxr = lr & 31;
            g_blabel[bi] = (tr * 16 + byr) * WB + (tw * 32 + bxr);
            g_bflag[bi]  = 0;
        }
        g_bmask[bi] = bmv;
    }
    __syncthreads();
    if (tid == 0) g_scnt[tile] = scnt;
}

// ---- global union-find (cross-tile) ----
__device__ __forceinline__ int uf_find(int x) {
    int p = g_blabel[x];
    while (p != x) {
        int gp = g_blabel[p];
        if (gp != p) g_blabel[x] = gp;
        x = p; p = gp;
    }
    return x;
}
__device__ __forceinline__ int uf_find_ro(int x) {
    int p = g_blabel[x];
    while (p != x) { x = p; p = g_blabel[x]; }
    return x;
}
__device__ __forceinline__ void uf_union(int i, int j) {
    int a = uf_find(i), b = uf_find(j);
    while (a != b) {
        int hi = a > b ? a : b;
        int lo = a > b ? b : a;
        int old = atomicCAS(&g_blabel[hi], hi, lo);
        if (old == hi) break;
        a = uf_find(old);
        b = uf_find(lo);
    }
}

// K2: cross-tile merge over ENUMERATED border blocks only (62 per tile)
#define NBORDER 62
__global__ __launch_bounds__(256) void k_merge() {
    int t = blockIdx.x * blockDim.x + threadIdx.x;
    if (t >= NTILE * NBORDER) return;
    int tile = t / NBORDER, slot = t - tile * NBORDER;
    int tr = tile >> 3, tw = tile & 7;
    int byt, bxt;
    if (slot < 32)      { byt = 15;        bxt = slot; }       // south row
    else if (slot < 47) { byt = slot - 32; bxt = 31;   }       // east col (byt 0..14)
    else                { byt = slot - 47; bxt = 0;    }       // west col (byt 0..14)
    int bx = tw * 32 + bxt, by = tr * 16 + byt;
    int bi = by * WB + bx;

    unsigned char m = g_bmask[bi];
    if (!(m & 0xF)) return;
    bool eB = (bxt == 31), sB = (byt == 15), wB = (bxt == 0);

    if (eB && bx + 1 < WB && (m & 0xA) && (g_bmask[bi + 1] & 0x5)) uf_union(bi, bi + 1);
    if (by + 1 < HB) {
        if (sB && (m & 0xC) && (g_bmask[bi + WB] & 0x3)) uf_union(bi, bi + WB);
        if ((sB | eB) && (m & 0x8) && bx + 1 < WB && (g_bmask[bi + WB + 1] & 0x1)) uf_union(bi, bi + WB + 1);
        if ((sB | wB) && (m & 0x4) && bx > 0 && (g_bmask[bi + WB - 1] & 0x2)) uf_union(bi, bi + WB - 1);
    }
}

// K3: compacted — only strong local roots walk to their final root
__global__ __launch_bounds__(64) void k_sflag() {
    int tile = blockIdx.x;
    int cnt = g_scnt[tile];
    for (int i = threadIdx.x; i < cnt; i += 64)
        g_bflag[uf_find_ro(g_slist[tile * 512 + i])] = 1;
}

// K4: ±1 output, 8 pixels/thread (2x4 patch = both rows of 2 blocks), 6x float4 stores
__global__ __launch_bounds__(256) void k_out(float* __restrict__ out) {
    int t = blockIdx.x * blockDim.x + threadIdx.x;   // NPIX/8 threads
    if (t >= NPIX / 8) return;
    int pw = t & 127, py = t >> 7;
    int bi0 = py * WB + pw * 2;

    unsigned char m0 = g_bmask[bi0], m1 = g_bmask[bi0 + 1];
    bool f0 = false, f1 = false;
    if (m0 & 0xF) f0 = (g_bflag[uf_find_ro(bi0)] != 0);
    if (m1 & 0xF) f1 = (g_bflag[uf_find_ro(bi0 + 1)] != 0);

    float4 v0 = make_float4(((m0 & 1) && f0) ? 1.0f : -1.0f,
                            ((m0 & 2) && f0) ? 1.0f : -1.0f,
                            ((m1 & 1) && f1) ? 1.0f : -1.0f,
                            ((m1 & 2) && f1) ? 1.0f : -1.0f);
    float4 v1 = make_float4(((m0 & 4) && f0) ? 1.0f : -1.0f,
                            ((m0 & 8) && f0) ? 1.0f : -1.0f,
                            ((m1 & 4) && f1) ? 1.0f : -1.0f,
                            ((m1 & 8) && f1) ? 1.0f : -1.0f);

    int r = py * 2;                       // top pixel row (r and r+1 in same image)
    int b = r >> 9, h = r & 511;
    size_t base = ((size_t)(b * 3) * 512 + h) * 512 + pw * 4;
    *(float4*)&out[base]                       = v0;
    *(float4*)&out[base + 512]                 = v1;
    *(float4*)&out[base + 512 * 512]           = v0;
    *(float4*)&out[base + 512 * 512 + 512]     = v1;
    *(float4*)&out[base + 2 * 512 * 512]       = v0;
    *(float4*)&out[base + 2 * 512 * 512 + 512] = v1;
}

extern "C" void kernel_launch(void* const* d_in, const int* in_sizes, int n_in,
                              void* d_out, int out_size) {
    const float* x = (const float*)d_in[0];
    float* out = (float*)d_out;
    k_gradnms<<<NTILE, 256>>>(x);
    k_merge<<<(NTILE * NBORDER + 255) / 256, 256>>>();
    k_sflag<<<NTILE, 64>>>();
    k_out<<<NPIX / 8 / 256, 256>>>(out);
}